// round 16
// baseline (speedup 1.0000x reference)
#include <cuda_runtime.h>
#include <math.h>

#define N_NODES 50000
#define N_EDGES 800000
#define N_GRAPHS 128
#define NEG_SLOPE 0.2f

// ---------------- scratch (device globals) ----------------
__device__ float g_el1[N_NODES * 3];
__device__ float g_er1[N_NODES * 3];
__device__ __align__(16) float g_x1[N_NODES * 96];    // POST-relu layer-1 output

__device__ float g_el2[N_NODES * 3];
__device__ float g_er2[N_NODES * 3];
__device__ __align__(16) float g_u2[N_NODES * 288];   // aggregated relu(x1) per head

__device__ __align__(16) float4 g_a4[N_EDGES];        // {w0,w1,w2, bits(src)}: w = exp(leaky(logit))

__device__ float g_w1al[30], g_w1ar[30];              // W1 @ al1 / ar1   [h][d<10]
__device__ float g_w2al[288], g_w2ar[288];            // W2 @ al2 / ar2   [h][k<96]

__device__ float g_pool[N_GRAPHS * 192];
__device__ float g_cnt[N_GRAPHS];

// CSR scratch
__device__ int g_deg[N_NODES];
__device__ int g_off[N_NODES + 1];
__device__ int g_cur[N_NODES];
__device__ int g_esrc[N_EDGES];
__device__ int g_edst[N_EDGES];

// ---------------- init ----------------
__global__ void k_init(const int* __restrict__ dummy) {
    int i = blockIdx.x * blockDim.x + threadIdx.x;
    if (i < N_NODES) g_deg[i] = 0;
    if (i < N_GRAPHS * 192) g_pool[i] = 0.0f;
    if (i < N_GRAPHS)       g_cnt[i] = 0.0f;
}

// ---------------- CSR build: hist + graph-count fused ----------------
__global__ void k_hist(const int* __restrict__ dst, const int* __restrict__ gid) {
    int e = blockIdx.x * blockDim.x + threadIdx.x;
    if (e < N_EDGES) atomicAdd(&g_deg[dst[e]], 1);
    if (e < N_NODES) atomicAdd(&g_cnt[gid[e]], 1.0f);
}

#define SCAN_T 1024
#define SCAN_CHUNK ((N_NODES + SCAN_T - 1) / SCAN_T)    // 49
__global__ void k_scan(const int* __restrict__ dst_unused) {
    __shared__ int psum[SCAN_T];
    int t = threadIdx.x;
    int lo = t * SCAN_CHUNK;
    int hi = (lo + SCAN_CHUNK < N_NODES) ? (lo + SCAN_CHUNK) : N_NODES;
    int s = 0;
    for (int n = lo; n < hi; n++) s += g_deg[n];
    psum[t] = s;
    __syncthreads();
    if (t == 0) {
        int run = 0;
        for (int i = 0; i < SCAN_T; i++) { int tmp = psum[i]; psum[i] = run; run += tmp; }
    }
    __syncthreads();
    int run = psum[t];
    for (int n = lo; n < hi; n++) {
        g_off[n] = run;
        g_cur[n] = run;
        run += g_deg[n];
    }
    if (t == 0) g_off[N_NODES] = N_EDGES;
}

// ---------------- scatter + layer-1 logits fused ----------------
// el1/er1 are ready (k_el1 runs before). Computes sorted position p, writes
// esrc/edst AND the packed exp-weights in one pass.
__global__ void k_scatter(const int* __restrict__ src, const int* __restrict__ dst) {
    int e = blockIdx.x * blockDim.x + threadIdx.x;
    if (e >= N_EDGES) return;
    int s = src[e], d = dst[e];
    int p = atomicAdd(&g_cur[d], 1);
    g_esrc[p] = s;
    g_edst[p] = d;
    float v0 = g_el1[s * 3 + 0] + g_er1[d * 3 + 0];
    float v1 = g_el1[s * 3 + 1] + g_er1[d * 3 + 1];
    float v2 = g_el1[s * 3 + 2] + g_er1[d * 3 + 2];
    v0 = (v0 > 0.f) ? v0 : NEG_SLOPE * v0;
    v1 = (v1 > 0.f) ? v1 : NEG_SLOPE * v1;
    v2 = (v2 > 0.f) ? v2 : NEG_SLOPE * v2;
    g_a4[p] = make_float4(expf(v0), expf(v1), expf(v2), __int_as_float(s));
}

// ---------------- precompute projected attention vectors (proven) ----------------
__global__ void k_prew(const float* __restrict__ W1, const float* __restrict__ al1,
                       const float* __restrict__ ar1, const float* __restrict__ W2,
                       const float* __restrict__ al2, const float* __restrict__ ar2) {
    int t = threadIdx.x;   // 288 threads
    if (t < 30) {
        int h = t / 10, d = t - 10 * h;
        float sl = 0.f, sr = 0.f;
#pragma unroll
        for (int j = 0; j < 32; j++) {
            float w = W1[d * 96 + h * 32 + j];
            sl = fmaf(w, al1[h * 32 + j], sl);
            sr = fmaf(w, ar1[h * 32 + j], sr);
        }
        g_w1al[t] = sl; g_w1ar[t] = sr;
    }
    if (t < 288) {
        int h = t / 96, k = t - 96 * h;
        float sl = 0.f, sr = 0.f;
#pragma unroll 8
        for (int j = 0; j < 64; j++) {
            float w = W2[k * 192 + h * 64 + j];
            sl = fmaf(w, al2[h * 64 + j], sl);
            sr = fmaf(w, ar2[h * 64 + j], sr);
        }
        g_w2al[t] = sl; g_w2ar[t] = sr;
    }
}

// ---------------- layer 1 el/er directly from features (proven) ----------------
__global__ void k_el1(const float* __restrict__ feat) {
    int n = blockIdx.x * blockDim.x + threadIdx.x;
    if (n >= N_NODES) return;
    float f[10];
#pragma unroll
    for (int d = 0; d < 10; d++) f[d] = feat[n * 10 + d];
#pragma unroll
    for (int h = 0; h < 3; h++) {
        float el = 0.f, er = 0.f;
#pragma unroll
        for (int d = 0; d < 10; d++) {
            el = fmaf(f[d], g_w1al[h * 10 + d], el);
            er = fmaf(f[d], g_w1ar[h * 10 + d], er);
        }
        g_el1[n * 3 + h] = el;
        g_er1[n * 3 + h] = er;
    }
}

// ---------------- layer-2 logits (proven) ----------------
__global__ void k_logits2(const int* __restrict__ a, const int* __restrict__ b) {
    int p = blockIdx.x * blockDim.x + threadIdx.x;
    if (p >= N_EDGES) return;
    int sv = g_esrc[p], dv = g_edst[p];
    float v0 = g_el2[sv * 3 + 0] + g_er2[dv * 3 + 0];
    float v1 = g_el2[sv * 3 + 1] + g_er2[dv * 3 + 1];
    float v2 = g_el2[sv * 3 + 2] + g_er2[dv * 3 + 2];
    v0 = (v0 > 0.f) ? v0 : NEG_SLOPE * v0;
    v1 = (v1 > 0.f) ? v1 : NEG_SLOPE * v1;
    v2 = (v2 > 0.f) ? v2 : NEG_SLOPE * v2;
    g_a4[p] = make_float4(expf(v0), expf(v1), expf(v2), __int_as_float(sv));
}

// ---------------- aggregation layer 1 COMMUTED (proven); pure LDG+FMA ----------
__global__ void k_agg1c(const float* __restrict__ feat, const float* __restrict__ W1) {
    __shared__ float u1s[8][32];
    int wid = threadIdx.x >> 5, lane = threadIdx.x & 31;
    int n = (blockIdx.x * blockDim.x + threadIdx.x) >> 5;   // grid exactly covers 50000
    bool act = lane < 30;
    int hsel = lane / 10; if (hsel > 2) hsel = 2;
    int d = lane - hsel * 10; if (!act) d = 0;
    int b0 = g_off[n], b1 = g_off[n + 1];
    float s0 = 0.f, s1 = 0.f, s2 = 0.f, acc = 0.f;
#pragma unroll 2
    for (int p = b0; p < b1; p++) {
        float4 av = g_a4[p];
        int sv = __float_as_int(av.w);
        float eh = (hsel == 0) ? av.x : (hsel == 1) ? av.y : av.z;
        float fv = act ? feat[sv * 10 + d] : 0.f;
        acc = fmaf(eh, fv, acc);
        s0 += av.x; s1 += av.y; s2 += av.z;
    }
    float sh = (hsel == 0) ? s0 : (hsel == 1) ? s1 : s2;
    u1s[wid][lane] = acc / (sh + 1e-16f);
    __syncwarp();
#pragma unroll
    for (int t = 0; t < 3; t++) {
        int o = lane + (t << 5);
        float x = 0.f;
#pragma unroll
        for (int dd = 0; dd < 10; dd++)
            x = fmaf(u1s[wid][t * 10 + dd], __ldg(&W1[dd * 96 + o]), x);
        g_x1[n * 96 + o] = fmaxf(x, 0.f);    // relu fused
    }
}

// ---------------- layer 2 el/er from relu(x1) (proven) ----------------
__global__ void k_el2(const int* __restrict__ dummy) {
    int i = blockIdx.x * blockDim.x + threadIdx.x;
    if (i >= N_NODES * 3) return;
    int n = i / 3, h = i - n * 3;
    float el = 0.f, er = 0.f;
#pragma unroll 8
    for (int k = 0; k < 96; k++) {
        float x = g_x1[n * 96 + k];
        el = fmaf(x, g_w2al[h * 96 + k], el);
        er = fmaf(x, g_w2ar[h * 96 + k], er);
    }
    g_el2[i] = el; g_er2[i] = er;
}

// ---------------- aggregation layer 2 (proven); pure LDG+FMA ----------------
__global__ void k_agg2u(const int* __restrict__ dummy) {
    int n = (blockIdx.x * blockDim.x + threadIdx.x) >> 5;
    if (n >= N_NODES) return;
    int lane = threadIdx.x & 31;
    bool act = lane < 24;
    int b0 = g_off[n], b1 = g_off[n + 1];
    float s0 = 0.f, s1 = 0.f, s2 = 0.f;
    float4 A0 = make_float4(0.f, 0.f, 0.f, 0.f);
    float4 A1 = A0, A2 = A0;
#pragma unroll 2
    for (int p = b0; p < b1; p++) {
        float4 av = g_a4[p];
        int sv = __float_as_int(av.w);
        if (act) {
            float4 x = *reinterpret_cast<const float4*>(&g_x1[sv * 96 + lane * 4]);
            A0.x = fmaf(av.x, x.x, A0.x); A0.y = fmaf(av.x, x.y, A0.y);
            A0.z = fmaf(av.x, x.z, A0.z); A0.w = fmaf(av.x, x.w, A0.w);
            A1.x = fmaf(av.y, x.x, A1.x); A1.y = fmaf(av.y, x.y, A1.y);
            A1.z = fmaf(av.y, x.z, A1.z); A1.w = fmaf(av.y, x.w, A1.w);
            A2.x = fmaf(av.z, x.x, A2.x); A2.y = fmaf(av.z, x.y, A2.y);
            A2.z = fmaf(av.z, x.z, A2.z); A2.w = fmaf(av.z, x.w, A2.w);
        }
        s0 += av.x; s1 += av.y; s2 += av.z;
    }
    if (act) {
        float i0 = 1.0f / (s0 + 1e-16f);
        float i1 = 1.0f / (s1 + 1e-16f);
        float i2 = 1.0f / (s2 + 1e-16f);
        float* u = &g_u2[n * 288];
        *reinterpret_cast<float4*>(&u[lane * 4]) =
            make_float4(A0.x * i0, A0.y * i0, A0.z * i0, A0.w * i0);
        *reinterpret_cast<float4*>(&u[96 + lane * 4]) =
            make_float4(A1.x * i1, A1.y * i1, A1.z * i1, A1.w * i1);
        *reinterpret_cast<float4*>(&u[192 + lane * 4]) =
            make_float4(A2.x * i2, A2.y * i2, A2.z * i2, A2.w * i2);
    }
}

// ---------------- gemm2 + fused pooling (proven) ----------
#define GT 8
__global__ void k_gemm2pool(const float* __restrict__ W2, const int* __restrict__ gid) {
    __shared__ float us[GT][290];   // even pad -> 8B-aligned float2 at even k
    __shared__ int gids[GT];
    int o = threadIdx.x;            // 0..191
    int base = blockIdx.x * GT;     // 6250 full blocks
    for (int idx = threadIdx.x; idx < GT * 288; idx += 192) {
        int i = idx / 288, k = idx - i * 288;
        us[i][k] = g_u2[(base + i) * 288 + k];
    }
    if (threadIdx.x < GT) gids[threadIdx.x] = gid[base + threadIdx.x];
    __syncthreads();
    int hbase = (o >> 6) * 96;
    float acc[GT];
#pragma unroll
    for (int i = 0; i < GT; i++) acc[i] = 0.f;
    for (int k = 0; k < 96; k += 2) {
        float w0 = __ldg(&W2[k * 192 + o]);
        float w1 = __ldg(&W2[(k + 1) * 192 + o]);
#pragma unroll
        for (int i = 0; i < GT; i++) {
            float2 uv = *reinterpret_cast<const float2*>(&us[i][hbase + k]);
            acc[i] = fmaf(uv.x, w0, acc[i]);
            acc[i] = fmaf(uv.y, w1, acc[i]);
        }
    }
    float run = 0.f;
    int cur = gids[0];
#pragma unroll
    for (int i = 0; i < GT; i++) {
        int g = gids[i];
        if (g != cur) {
            atomicAdd(&g_pool[cur * 192 + o], run);
            run = 0.f; cur = g;
        }
        run += fmaxf(acc[i], 0.f);
    }
    atomicAdd(&g_pool[cur * 192 + o], run);
}

// ---------------- final MLP (proven) ----------------
__global__ void k_mlp(const float* __restrict__ d1w, const float* __restrict__ d1b,
                      const float* __restrict__ d2w, const float* __restrict__ d2b,
                      float* __restrict__ out) {
    int g = blockIdx.x;
    int j = threadIdx.x;  // 0..63
    __shared__ float ps[192];
    __shared__ float hred[64];
    float inv = 1.0f / fmaxf(g_cnt[g], 1.0f);
    for (int k = j; k < 192; k += 64) ps[k] = g_pool[g * 192 + k] * inv;
    __syncthreads();
    float acc = d1b[j];
#pragma unroll 8
    for (int k = 0; k < 192; k++) acc = fmaf(ps[k], __ldg(&d1w[k * 64 + j]), acc);
    acc = fmaxf(acc, 0.f);
    hred[j] = acc * __ldg(&d2w[j]);
    __syncthreads();
    for (int s = 32; s > 0; s >>= 1) {
        if (j < s) hred[j] += hred[j + s];
        __syncthreads();
    }
    if (j == 0) out[g] = hred[0] + d2b[0];
}

// ---------------- launch ----------------
extern "C" void kernel_launch(void* const* d_in, const int* in_sizes, int n_in,
                              void* d_out, int out_size) {
    const float* feature = (const float*)d_in[0];
    const int*   src     = (const int*)d_in[1];
    const int*   dst     = (const int*)d_in[2];
    const int*   gid     = (const int*)d_in[3];
    const float* W1      = (const float*)d_in[4];
    const float* al1     = (const float*)d_in[5];
    const float* ar1     = (const float*)d_in[6];
    const float* W2      = (const float*)d_in[7];
    const float* al2     = (const float*)d_in[8];
    const float* ar2     = (const float*)d_in[9];
    const float* d1w     = (const float*)d_in[10];
    const float* d1b     = (const float*)d_in[11];
    const float* d2w     = (const float*)d_in[12];
    const float* d2b     = (const float*)d_in[13];
    float* out = (float*)d_out;

    // init + projections + el1 (needed before fused scatter+logits1)
    k_init<<<(N_NODES + 255) / 256, 256>>>(dst);
    k_prew<<<1, 288>>>(W1, al1, ar1, W2, al2, ar2);
    k_el1<<<(N_NODES + 255) / 256, 256>>>(feature);

    // CSR build (hist fused with graph-count; scatter fused with logits1)
    k_hist<<<(N_EDGES + 255) / 256, 256>>>(dst, gid);
    k_scan<<<1, SCAN_T>>>(dst);
    k_scatter<<<(N_EDGES + 255) / 256, 256>>>(src, dst);

    // ---- layer 1 aggregation ----
    k_agg1c<<<N_NODES / 8, 256>>>(feature, W1);

    // ---- layer 2 ----
    k_el2<<<(N_NODES * 3 + 255) / 256, 256>>>(src);
    k_logits2<<<(N_EDGES + 255) / 256, 256>>>(src, dst);
    k_agg2u<<<(N_NODES * 32 + 255) / 256, 256>>>(src);
    k_gemm2pool<<<N_NODES / GT, 192>>>(W2, gid);

    // ---- MLP ----
    k_mlp<<<N_GRAPHS, 64>>>(d1w, d1b, d2w, d2b, out);
}